// round 2
// baseline (speedup 1.0000x reference)
#include <cuda_runtime.h>
#include <cstdint>
#include <cstdio>

#define LSEQ 4096
#define HID  512
#define TH3  1536      // 3*HID
#define GB   32        // blocks per GRU direction
#define SLICE 16       // HID / GB
#define NROW 48        // 3*SLICE rows of w_hh per block
#define KF1  9216      // 1024 * 9 augmented K for KAN layer 1
#define KF2  4608      // 512 * 9  augmented K for KAN layer 2

// ---------------- scratch (device globals; no allocation allowed) ----------
__device__ float g_gi[2][LSEQ * TH3];        // input gates, fwd/bwd
__device__ float g_dirout[2][LSEQ * HID];    // GRU outputs per direction
__device__ float g_A1[LSEQ * KF1];           // augmented features KAN1
__device__ float g_W1[HID * KF1];            // augmented weights  KAN1
__device__ float g_A2[LSEQ * KF2];
__device__ float g_W2[HID * KF2];
__device__ float g_a2[LSEQ * HID];           // sigmoid output of KAN2
__device__ float g_h[2][2][HID];             // [dir][parity][i] hidden double buffer
__device__ int   g_flag[2][GB];              // per-block completed-step flags (1 line/dir)
__device__ float g_yp[32][HID];              // partial sums for final reduction

// ---------------- init: reset recurrence state each replay -----------------
__global__ void k_init() {
    int i = blockIdx.x * blockDim.x + threadIdx.x;
    if (i < 2 * 2 * HID) ((float*)g_h)[i] = 0.f;
    if (i < 2 * GB) ((int*)g_flag)[i] = -1;
}

// ---------------- fp32 GEMM: C[M,N] = act(A[M,K] @ B[N,K]^T + bias) --------
// BM=128, BN=128, BK=16, 256 threads, 8x8 register tile per thread.
template <int ACT>
__global__ void __launch_bounds__(256, 1) k_gemm(
    const float* __restrict__ A, const float* __restrict__ B,
    const float* __restrict__ bias, float* __restrict__ C,
    int M, int N, int K)
{
    const int BM = 128, BN = 128, BK = 16;
    __shared__ float As[BK][BM + 4];
    __shared__ float Bs[BK][BN + 4];
    int bm = blockIdx.y, bn = blockIdx.x;
    int tid = threadIdx.x;
    int tx = tid & 15;    // col group (x8)
    int ty = tid >> 4;    // row group (x8)
    const float* Ab = A + (size_t)bm * BM * K;
    const float* Bb = B + (size_t)bn * BN * K;

    float acc[8][8];
#pragma unroll
    for (int i = 0; i < 8; i++)
#pragma unroll
        for (int j = 0; j < 8; j++) acc[i][j] = 0.f;

    for (int k0 = 0; k0 < K; k0 += BK) {
#pragma unroll
        for (int it = 0; it < 2; it++) {
            int v = tid + 256 * it;
            int r = v >> 2, kq = (v & 3) * 4;
            float4 a = *(const float4*)(Ab + (size_t)r * K + k0 + kq);
            As[kq + 0][r] = a.x; As[kq + 1][r] = a.y;
            As[kq + 2][r] = a.z; As[kq + 3][r] = a.w;
            float4 b = *(const float4*)(Bb + (size_t)r * K + k0 + kq);
            Bs[kq + 0][r] = b.x; Bs[kq + 1][r] = b.y;
            Bs[kq + 2][r] = b.z; Bs[kq + 3][r] = b.w;
        }
        __syncthreads();
#pragma unroll
        for (int kk = 0; kk < BK; kk++) {
            float ra[8], rb[8];
#pragma unroll
            for (int i = 0; i < 8; i += 4)
                *(float4*)&ra[i] = *(const float4*)&As[kk][ty * 8 + i];
#pragma unroll
            for (int j = 0; j < 8; j += 4)
                *(float4*)&rb[j] = *(const float4*)&Bs[kk][tx * 8 + j];
#pragma unroll
            for (int i = 0; i < 8; i++)
#pragma unroll
                for (int j = 0; j < 8; j++) acc[i][j] = fmaf(ra[i], rb[j], acc[i][j]);
        }
        __syncthreads();
    }

#pragma unroll
    for (int i = 0; i < 8; i++) {
        int row = bm * BM + ty * 8 + i;
#pragma unroll
        for (int j = 0; j < 8; j++) {
            int col = bn * BN + tx * 8 + j;
            float v = acc[i][j];
            if (bias) v += bias[col];
            if (ACT == 1) v = v > 0.f ? v : 0.f;
            else if (ACT == 2) v = 1.f / (1.f + expf(-v));
            C[(size_t)row * N + col] = v;
        }
    }
}

// ---------------- GRU recurrence: persistent, flag-synced ------------------
// grid (GB, 2): blockIdx.y = direction. Each block owns SLICE h-indices,
// holds its 48 w_hh rows in registers (96 floats / thread).
__global__ void __launch_bounds__(256, 1) k_gru(
    const float* __restrict__ whhf, const float* __restrict__ whhb,
    const float* __restrict__ bhhf, const float* __restrict__ bhhb)
{
    int dir = blockIdx.y;
    int b   = blockIdx.x;
    const float* gi  = g_gi[dir];
    float*       out = g_dirout[dir];
    const float* whh = dir ? whhb : whhf;
    const float* bhh = dir ? bhhb : bhhf;
    int i0 = b * SLICE;
    int tid = threadIdx.x, lane = tid & 31, warp = tid >> 5;

    __shared__ float h_s[HID];
    __shared__ float dot_s[NROW];
    __shared__ float gi_s[NROW];
    __shared__ float bhh_s[NROW];

    // Load this block's 48 w_hh rows into registers.
    // thread (warp, lane) owns rows q = warp*6 + r, cols lane + 32*m
    float w[6][16];
#pragma unroll
    for (int r = 0; r < 6; r++) {
        int q = warp * 6 + r;
        int grow = (q / SLICE) * HID + i0 + (q % SLICE);
#pragma unroll
        for (int m = 0; m < 16; m++)
            w[r][m] = whh[(size_t)grow * HID + lane + 32 * m];
    }
    if (tid < NROW)
        bhh_s[tid] = bhh[(tid / SLICE) * HID + i0 + (tid % SLICE)];
    __syncthreads();

    for (int t = 0; t < LSEQ; t++) {
        int tt = dir ? (LSEQ - 1 - t) : t;

        // Prefetch gi for this step BEFORE the spin (hides DRAM latency)
        float giv = 0.f;
        if (tid < NROW)
            giv = __ldg(&gi[(size_t)tt * TH3 + (tid / SLICE) * HID + i0 + (tid % SLICE)]);

        // Wait for all blocks of this direction to finish step t-1.
        if (t > 0) {
            if (tid < 32) {
                while (1) {
                    int f = *(volatile int*)&g_flag[dir][tid];
                    if (__all_sync(0xffffffffu, f >= t - 1)) break;
                    __nanosleep(40);
                }
            }
            __syncthreads();
        }

        // Load full h_prev (bypass L1: written by other SMs)
        const float* hg = g_h[dir][t & 1];
        for (int k = tid; k < HID; k += 256) h_s[k] = __ldcg(&hg[k]);
        __syncthreads();

        float hv[16];
#pragma unroll
        for (int m = 0; m < 16; m++) hv[m] = h_s[lane + 32 * m];

        float acc[6];
#pragma unroll
        for (int r = 0; r < 6; r++) {
            float a = 0.f;
#pragma unroll
            for (int m = 0; m < 16; m++) a = fmaf(w[r][m], hv[m], a);
            acc[r] = a;
        }
#pragma unroll
        for (int r = 0; r < 6; r++) {
#pragma unroll
            for (int off = 16; off > 0; off >>= 1)
                acc[r] += __shfl_down_sync(0xffffffffu, acc[r], off);
        }
        if (lane == 0) {
#pragma unroll
            for (int r = 0; r < 6; r++) dot_s[warp * 6 + r] = acc[r];
        }
        if (tid < NROW) gi_s[tid] = giv;
        __syncthreads();

        if (tid < SLICE) {
            int j = tid, i = i0 + j;
            float ir  = gi_s[j];
            float iz  = gi_s[SLICE + j];
            float inn = gi_s[2 * SLICE + j];
            float hr = dot_s[j]             + bhh_s[j];
            float hz = dot_s[SLICE + j]     + bhh_s[SLICE + j];
            float hn = dot_s[2 * SLICE + j] + bhh_s[2 * SLICE + j];
            float rg = 1.f / (1.f + expf(-(ir + hr)));
            float zg = 1.f / (1.f + expf(-(iz + hz)));
            float ng = tanhf(inn + rg * hn);
            float hnew = (1.f - zg) * ng + zg * h_s[i];
            g_h[dir][(t + 1) & 1][i] = hnew;
            out[(size_t)tt * HID + i] = hnew;
            __threadfence();   // release: h stores visible before flag
        }
        __syncthreads();
        if (tid == 0) *(volatile int*)&g_flag[dir][b] = t;
    }
}

// ---------------- KAN feature expansion ------------------------------------
// grid over grid_range [-1,1], GS=5, K=3: g[j] = 0.4*(j-3) - 1, j=0..11
__device__ __forceinline__ void kan_feats(float x, float* f) {
    f[0] = x / (1.f + expf(-x));   // silu
    float b[11];
#pragma unroll
    for (int j = 0; j < 11; j++) {
        float gj  = 0.4f * (float)(j - 3) - 1.0f;
        float gj1 = 0.4f * (float)(j - 2) - 1.0f;
        b[j] = (x >= gj && x < gj1) ? 1.f : 0.f;
    }
#pragma unroll
    for (int k = 1; k <= 3; k++) {
#pragma unroll
        for (int j = 0; j < 11; j++) {
            if (j + k < 11) {
                float gj   = 0.4f * (float)(j - 3)     - 1.f;
                float gjk  = 0.4f * (float)(j + k - 3) - 1.f;
                float gj1  = 0.4f * (float)(j - 2)     - 1.f;
                float gjk1 = 0.4f * (float)(j + k - 2) - 1.f;
                b[j] = (x - gj) / (gjk - gj) * b[j]
                     + (gjk1 - x) / (gjk1 - gj1) * b[j + 1];
            }
        }
    }
#pragma unroll
    for (int q = 0; q < 8; q++) f[1 + q] = b[q];
}

__global__ void k_expand1(float* __restrict__ A) {
    int idx = blockIdx.x * 256 + threadIdx.x;   // n*1024 + i
    int n = idx >> 10, i = idx & 1023;
    float x = (i < HID) ? g_dirout[0][n * HID + i]
                        : g_dirout[1][n * HID + (i - HID)];
    float f[9]; kan_feats(x, f);
    float* dst = A + (size_t)n * KF1 + i * 9;
#pragma unroll
    for (int c = 0; c < 9; c++) dst[c] = f[c];
}

__global__ void k_expand2(const float* __restrict__ a1, float* __restrict__ A) {
    int idx = blockIdx.x * 256 + threadIdx.x;   // n*512 + i
    float x = a1[idx];
    int n = idx >> 9, i = idx & 511;
    float f[9]; kan_feats(x, f);
    float* dst = A + (size_t)n * KF2 + i * 9;
#pragma unroll
    for (int c = 0; c < 9; c++) dst[c] = f[c];
}

__global__ void k_buildW(const float* __restrict__ bw, const float* __restrict__ sw,
                         const float* __restrict__ sc, float* __restrict__ W, int INF) {
    int idx = blockIdx.x * 256 + threadIdx.x;
    if (idx >= HID * INF) return;
    int i = idx % INF;
    int o = idx / INF;
    float s = sc[idx];
    float* dst = W + (size_t)o * INF * 9 + i * 9;
    dst[0] = bw[idx];
#pragma unroll
    for (int q = 0; q < 8; q++) dst[1 + q] = sw[(size_t)idx * 8 + q] * s;
}

// ---------------- final reduction y = a2^T p -------------------------------
__global__ void k_ypart(const float* __restrict__ p) {
    int bb = blockIdx.x;         // 32 blocks, 128 rows each
    int o  = threadIdx.x;        // 512 threads
    float acc = 0.f;
    int n0 = bb * 128;
#pragma unroll 4
    for (int n = n0; n < n0 + 128; n++)
        acc = fmaf(g_a2[(size_t)n * HID + o], p[n], acc);
    g_yp[bb][o] = acc;
}

__global__ void k_yfinal(float* __restrict__ y) {
    int o = blockIdx.x * 256 + threadIdx.x;
    float acc = 0.f;
#pragma unroll
    for (int c = 0; c < 32; c++) acc += g_yp[c][o];
    y[o] = acc;
}

// ---------------- launch ---------------------------------------------------
extern "C" void kernel_launch(void* const* d_in, const int* in_sizes, int n_in,
                              void* d_out, int out_size) {
    const float* h    = (const float*)d_in[0];
    const float* p    = (const float*)d_in[1];
    const float* wihf = (const float*)d_in[2];
    const float* whhf = (const float*)d_in[3];
    const float* bihf = (const float*)d_in[4];
    const float* bhhf = (const float*)d_in[5];
    const float* wihb = (const float*)d_in[6];
    const float* whhb = (const float*)d_in[7];
    const float* bihb = (const float*)d_in[8];
    const float* bhhb = (const float*)d_in[9];
    const float* bw1  = (const float*)d_in[10];
    const float* sw1  = (const float*)d_in[11];
    const float* sc1  = (const float*)d_in[12];
    const float* bw2  = (const float*)d_in[13];
    const float* sw2  = (const float*)d_in[14];
    const float* sc2  = (const float*)d_in[15];
    float* out = (float*)d_out;     // [0:512) = y, [512:) = a_1 (L,HID)

    float *gi_base, *A1, *W1, *A2, *W2, *a2;
    cudaGetSymbolAddress((void**)&gi_base, g_gi);
    cudaGetSymbolAddress((void**)&A1, g_A1);
    cudaGetSymbolAddress((void**)&W1, g_W1);
    cudaGetSymbolAddress((void**)&A2, g_A2);
    cudaGetSymbolAddress((void**)&W2, g_W2);
    cudaGetSymbolAddress((void**)&a2, g_a2);
    float* gi_f = gi_base;
    float* gi_b = gi_base + (size_t)LSEQ * TH3;

    k_init<<<8, 256>>>();

    // input-gate GEMMs: gi = h @ w_ih^T + b_ih
    dim3 ggi(TH3 / 128, LSEQ / 128);
    k_gemm<0><<<ggi, 256>>>(h, wihf, bihf, gi_f, LSEQ, TH3, HID);
    k_gemm<0><<<ggi, 256>>>(h, wihb, bihb, gi_b, LSEQ, TH3, HID);

    // recurrence, both directions concurrently
    k_gru<<<dim3(GB, 2), 256>>>(whhf, whhb, bhhf, bhhb);

    // KAN layer 1
    k_expand1<<<(LSEQ * 1024) / 256, 256>>>(A1);
    k_buildW<<<(HID * 1024 + 255) / 256, 256>>>(bw1, sw1, sc1, W1, 1024);
    k_gemm<1><<<dim3(HID / 128, LSEQ / 128), 256>>>(A1, W1, nullptr, out + HID, LSEQ, HID, KF1);

    // KAN layer 2
    k_expand2<<<(LSEQ * HID) / 256, 256>>>(out + HID, A2);
    k_buildW<<<(HID * HID + 255) / 256, 256>>>(bw2, sw2, sc2, W2, HID);
    k_gemm<2><<<dim3(HID / 128, LSEQ / 128), 256>>>(A2, W2, nullptr, a2, LSEQ, HID, KF2);

    // y = a2^T p (deterministic two-stage reduction)
    k_ypart<<<32, 512>>>(p);
    k_yfinal<<<2, 256>>>(out);
}

// round 6
// speedup vs baseline: 1.1781x; 1.1781x over previous
#include <cuda_runtime.h>
#include <cstdint>
#include <cstdio>

#define LSEQ 4096
#define HID  512
#define TH3  1536      // 3*HID
#define GB   32        // blocks per GRU direction
#define SLICE 16       // HID / GB
#define NROW 48        // 3*SLICE rows of w_hh per block
#define KF1  9216      // 1024 * 9 augmented K for KAN layer 1
#define KF2  4608      // 512 * 9  augmented K for KAN layer 2

// ---------------- scratch (device globals; no allocation allowed) ----------
__device__ float g_gi[2][LSEQ * TH3];        // input gates, fwd/bwd
__device__ float g_dirout[2][LSEQ * HID];    // GRU outputs per direction
__device__ float g_A1[LSEQ * KF1];           // augmented features KAN1
__device__ float g_W1[HID * KF1];            // augmented weights  KAN1
__device__ float g_A2[LSEQ * KF2];
__device__ float g_W2[HID * KF2];
__device__ float g_a2[LSEQ * HID];           // sigmoid output of KAN2
__device__ float g_h[2][2][HID];             // [dir][parity][i] hidden double buffer
__device__ int   g_flag[2][GB];              // per-block completed-step flags (1 line/dir)
__device__ float g_yp[32][HID];              // partial sums for final reduction

// ---------------- init: reset recurrence state each replay -----------------
__global__ void k_init() {
    int i = blockIdx.x * blockDim.x + threadIdx.x;
    if (i < 2 * 2 * HID) ((float*)g_h)[i] = 0.f;
    if (i < 2 * GB) ((int*)g_flag)[i] = -1;
}

// ---------------- TF32 tensor-core GEMM ------------------------------------
// C[M,N] = act(A[M,K] @ B[N,K]^T + bias), via mma.sync.m16n8k8.tf32.
// BM=BN=128, BK=32, 256 threads = 8 warps (2x4), warp tile 64x32.
// Smem [row][k] with PAD=36: staging float4 STS and fragment LDS both
// bank-conflict-free. Global loads for slab k+1 prefetched into registers
// while slab k computes.
#define GPAD 36

__device__ __forceinline__ uint32_t to_tf32(float x) {
    uint32_t r;
    asm("cvt.rna.tf32.f32 %0, %1;" : "=r"(r) : "f"(x));   // tf32 dest is .b32
    return r;
}
__device__ __forceinline__ float to_tf32f(float x) {
    return __uint_as_float(to_tf32(x));
}

__device__ __forceinline__ void mma_tf32(float* c, const uint32_t* a, const uint32_t* b) {
    asm volatile(
        "mma.sync.aligned.m16n8k8.row.col.f32.tf32.tf32.f32 "
        "{%0,%1,%2,%3}, {%4,%5,%6,%7}, {%8,%9}, {%0,%1,%2,%3};"
        : "+f"(c[0]), "+f"(c[1]), "+f"(c[2]), "+f"(c[3])
        : "r"(a[0]), "r"(a[1]), "r"(a[2]), "r"(a[3]), "r"(b[0]), "r"(b[1]));
}

template <int ACT>
__global__ void __launch_bounds__(256, 1) k_gemm(
    const float* __restrict__ A, const float* __restrict__ B,
    const float* __restrict__ bias, float* __restrict__ C,
    int M, int N, int K)
{
    __shared__ float As[128 * GPAD];
    __shared__ float Bs[128 * GPAD];
    int tid = threadIdx.x, lane = tid & 31, warp = tid >> 5;
    int wm = warp >> 2, wn = warp & 3;          // warp grid 2 (M) x 4 (N)
    int gid = lane >> 2, tig = lane & 3;
    int bm = blockIdx.y, bn = blockIdx.x;
    const float* Ab = A + (size_t)bm * 128 * K;
    const float* Bb = B + (size_t)bn * 128 * K;

    int r = tid >> 1, seg = (tid & 1) * 16;     // staging: row r, 16 cols

    float4 sa[4], sb[4];
    float acc[4][4][4];
#pragma unroll
    for (int mt = 0; mt < 4; mt++)
#pragma unroll
        for (int nt = 0; nt < 4; nt++)
#pragma unroll
            for (int q = 0; q < 4; q++) acc[mt][nt][q] = 0.f;

    // prefetch slab 0
#pragma unroll
    for (int i = 0; i < 4; i++) {
        sa[i] = *(const float4*)(Ab + (size_t)r * K + seg + 4 * i);
        sb[i] = *(const float4*)(Bb + (size_t)r * K + seg + 4 * i);
    }

    for (int k0 = 0; k0 < K; k0 += 32) {
        // stage regs -> smem (tf32-rounded)
#pragma unroll
        for (int i = 0; i < 4; i++) {
            float4 a = sa[i], b = sb[i];
            a.x = to_tf32f(a.x); a.y = to_tf32f(a.y);
            a.z = to_tf32f(a.z); a.w = to_tf32f(a.w);
            b.x = to_tf32f(b.x); b.y = to_tf32f(b.y);
            b.z = to_tf32f(b.z); b.w = to_tf32f(b.w);
            *(float4*)&As[r * GPAD + seg + 4 * i] = a;
            *(float4*)&Bs[r * GPAD + seg + 4 * i] = b;
        }
        __syncthreads();

        // prefetch next slab
        if (k0 + 32 < K) {
#pragma unroll
            for (int i = 0; i < 4; i++) {
                sa[i] = *(const float4*)(Ab + (size_t)r * K + k0 + 32 + seg + 4 * i);
                sb[i] = *(const float4*)(Bb + (size_t)r * K + k0 + 32 + seg + 4 * i);
            }
        }

#pragma unroll
        for (int ks = 0; ks < 4; ks++) {
            int kk = ks * 8;
            uint32_t bf[4][2];
#pragma unroll
            for (int nt = 0; nt < 4; nt++) {
                int n = wn * 32 + nt * 8 + gid;
                bf[nt][0] = __float_as_uint(Bs[n * GPAD + kk + tig]);
                bf[nt][1] = __float_as_uint(Bs[n * GPAD + kk + tig + 4]);
            }
#pragma unroll
            for (int mt = 0; mt < 4; mt++) {
                int m = wm * 64 + mt * 16;
                uint32_t af[4];
                af[0] = __float_as_uint(As[(m + gid) * GPAD + kk + tig]);
                af[1] = __float_as_uint(As[(m + gid + 8) * GPAD + kk + tig]);
                af[2] = __float_as_uint(As[(m + gid) * GPAD + kk + tig + 4]);
                af[3] = __float_as_uint(As[(m + gid + 8) * GPAD + kk + tig + 4]);
#pragma unroll
                for (int nt = 0; nt < 4; nt++)
                    mma_tf32(acc[mt][nt], af, bf[nt]);
            }
        }
        __syncthreads();
    }

    // epilogue: c0,c1 -> (row gid, col 2*tig, 2*tig+1); c2,c3 -> row gid+8
#pragma unroll
    for (int mt = 0; mt < 4; mt++) {
#pragma unroll
        for (int nt = 0; nt < 4; nt++) {
            int row0 = bm * 128 + wm * 64 + mt * 16 + gid;
            int col  = bn * 128 + wn * 32 + nt * 8 + 2 * tig;
            float v[4];
#pragma unroll
            for (int q = 0; q < 4; q++) v[q] = acc[mt][nt][q];
            if (bias) {
                float b0 = bias[col], b1 = bias[col + 1];
                v[0] += b0; v[1] += b1; v[2] += b0; v[3] += b1;
            }
            if (ACT == 1) {
#pragma unroll
                for (int q = 0; q < 4; q++) v[q] = v[q] > 0.f ? v[q] : 0.f;
            } else if (ACT == 2) {
#pragma unroll
                for (int q = 0; q < 4; q++) v[q] = 1.f / (1.f + expf(-v[q]));
            }
            *(float2*)&C[(size_t)row0 * N + col]       = make_float2(v[0], v[1]);
            *(float2*)&C[(size_t)(row0 + 8) * N + col] = make_float2(v[2], v[3]);
        }
    }
}

// ---------------- GRU recurrence: persistent, flag-synced ------------------
__global__ void __launch_bounds__(256, 1) k_gru(
    const float* __restrict__ whhf, const float* __restrict__ whhb,
    const float* __restrict__ bhhf, const float* __restrict__ bhhb)
{
    int dir = blockIdx.y;
    int b   = blockIdx.x;
    const float* gi  = g_gi[dir];
    float*       out = g_dirout[dir];
    const float* whh = dir ? whhb : whhf;
    const float* bhh = dir ? bhhb : bhhf;
    int i0 = b * SLICE;
    int tid = threadIdx.x, lane = tid & 31, warp = tid >> 5;

    __shared__ float h_s[HID];
    __shared__ float dot_s[NROW];
    __shared__ float gi_s[NROW];
    __shared__ float bhh_s[NROW];

    float w[6][16];
#pragma unroll
    for (int r = 0; r < 6; r++) {
        int q = warp * 6 + r;
        int grow = (q / SLICE) * HID + i0 + (q % SLICE);
#pragma unroll
        for (int m = 0; m < 16; m++)
            w[r][m] = whh[(size_t)grow * HID + lane + 32 * m];
    }
    if (tid < NROW)
        bhh_s[tid] = bhh[(tid / SLICE) * HID + i0 + (tid % SLICE)];
    __syncthreads();

    for (int t = 0; t < LSEQ; t++) {
        int tt = dir ? (LSEQ - 1 - t) : t;

        float giv = 0.f;
        if (tid < NROW)
            giv = __ldg(&gi[(size_t)tt * TH3 + (tid / SLICE) * HID + i0 + (tid % SLICE)]);

        if (t > 0) {
            if (tid < 32) {
                while (1) {
                    int f = *(volatile int*)&g_flag[dir][tid];
                    if (__all_sync(0xffffffffu, f >= t - 1)) break;
                    __nanosleep(40);
                }
            }
            __syncthreads();
        }

        const float* hg = g_h[dir][t & 1];
        for (int k = tid; k < HID; k += 256) h_s[k] = __ldcg(&hg[k]);
        __syncthreads();

        float hv[16];
#pragma unroll
        for (int m = 0; m < 16; m++) hv[m] = h_s[lane + 32 * m];

        float acc[6];
#pragma unroll
        for (int r = 0; r < 6; r++) {
            float a = 0.f;
#pragma unroll
            for (int m = 0; m < 16; m++) a = fmaf(w[r][m], hv[m], a);
            acc[r] = a;
        }
#pragma unroll
        for (int r = 0; r < 6; r++) {
#pragma unroll
            for (int off = 16; off > 0; off >>= 1)
                acc[r] += __shfl_down_sync(0xffffffffu, acc[r], off);
        }
        if (lane == 0) {
#pragma unroll
            for (int r = 0; r < 6; r++) dot_s[warp * 6 + r] = acc[r];
        }
        if (tid < NROW) gi_s[tid] = giv;
        __syncthreads();

        if (tid < SLICE) {
            int j = tid, i = i0 + j;
            float ir  = gi_s[j];
            float iz  = gi_s[SLICE + j];
            float inn = gi_s[2 * SLICE + j];
            float hr = dot_s[j]             + bhh_s[j];
            float hz = dot_s[SLICE + j]     + bhh_s[SLICE + j];
            float hn = dot_s[2 * SLICE + j] + bhh_s[2 * SLICE + j];
            float rg = 1.f / (1.f + expf(-(ir + hr)));
            float zg = 1.f / (1.f + expf(-(iz + hz)));
            float ng = tanhf(inn + rg * hn);
            float hnew = (1.f - zg) * ng + zg * h_s[i];
            g_h[dir][(t + 1) & 1][i] = hnew;
            out[(size_t)tt * HID + i] = hnew;
            __threadfence();   // release: h stores visible before flag
        }
        __syncthreads();
        if (tid == 0) *(volatile int*)&g_flag[dir][b] = t;
    }
}

// ---------------- KAN feature expansion ------------------------------------
__device__ __forceinline__ void kan_feats(float x, float* f) {
    f[0] = x / (1.f + expf(-x));   // silu
    float b[11];
#pragma unroll
    for (int j = 0; j < 11; j++) {
        float gj  = 0.4f * (float)(j - 3) - 1.0f;
        float gj1 = 0.4f * (float)(j - 2) - 1.0f;
        b[j] = (x >= gj && x < gj1) ? 1.f : 0.f;
    }
#pragma unroll
    for (int k = 1; k <= 3; k++) {
#pragma unroll
        for (int j = 0; j < 11; j++) {
            if (j + k < 11) {
                float gj   = 0.4f * (float)(j - 3)     - 1.f;
                float gjk  = 0.4f * (float)(j + k - 3) - 1.f;
                float gj1  = 0.4f * (float)(j - 2)     - 1.f;
                float gjk1 = 0.4f * (float)(j + k - 2) - 1.f;
                b[j] = (x - gj) / (gjk - gj) * b[j]
                     + (gjk1 - x) / (gjk1 - gj1) * b[j + 1];
            }
        }
    }
#pragma unroll
    for (int q = 0; q < 8; q++) f[1 + q] = b[q];
}

__global__ void k_expand1(float* __restrict__ A) {
    int idx = blockIdx.x * 256 + threadIdx.x;   // n*1024 + i
    int n = idx >> 10, i = idx & 1023;
    float x = (i < HID) ? g_dirout[0][n * HID + i]
                        : g_dirout[1][n * HID + (i - HID)];
    float f[9]; kan_feats(x, f);
    float* dst = A + (size_t)n * KF1 + i * 9;
#pragma unroll
    for (int c = 0; c < 9; c++) dst[c] = f[c];
}

__global__ void k_expand2(const float* __restrict__ a1, float* __restrict__ A) {
    int idx = blockIdx.x * 256 + threadIdx.x;   // n*512 + i
    float x = a1[idx];
    int n = idx >> 9, i = idx & 511;
    float f[9]; kan_feats(x, f);
    float* dst = A + (size_t)n * KF2 + i * 9;
#pragma unroll
    for (int c = 0; c < 9; c++) dst[c] = f[c];
}

__global__ void k_buildW(const float* __restrict__ bw, const float* __restrict__ sw,
                         const float* __restrict__ sc, float* __restrict__ W, int INF) {
    int idx = blockIdx.x * 256 + threadIdx.x;
    if (idx >= HID * INF) return;
    int i = idx % INF;
    int o = idx / INF;
    float s = sc[idx];
    float* dst = W + (size_t)o * INF * 9 + i * 9;
    dst[0] = bw[idx];
#pragma unroll
    for (int q = 0; q < 8; q++) dst[1 + q] = sw[(size_t)idx * 8 + q] * s;
}

// ---------------- final reduction y = a2^T p -------------------------------
__global__ void k_ypart(const float* __restrict__ p) {
    int bb = blockIdx.x;
    int o  = threadIdx.x;
    float acc = 0.f;
    int n0 = bb * 128;
#pragma unroll 4
    for (int n = n0; n < n0 + 128; n++)
        acc = fmaf(g_a2[(size_t)n * HID + o], p[n], acc);
    g_yp[bb][o] = acc;
}

__global__ void k_yfinal(float* __restrict__ y) {
    int o = blockIdx.x * 256 + threadIdx.x;
    float acc = 0.f;
#pragma unroll
    for (int c = 0; c < 32; c++) acc += g_yp[c][o];
    y[o] = acc;
}

// ---------------- launch ---------------------------------------------------
extern "C" void kernel_launch(void* const* d_in, const int* in_sizes, int n_in,
                              void* d_out, int out_size) {
    const float* h    = (const float*)d_in[0];
    const float* p    = (const float*)d_in[1];
    const float* wihf = (const float*)d_in[2];
    const float* whhf = (const float*)d_in[3];
    const float* bihf = (const float*)d_in[4];
    const float* bhhf = (const float*)d_in[5];
    const float* wihb = (const float*)d_in[6];
    const float* whhb = (const float*)d_in[7];
    const float* bihb = (const float*)d_in[8];
    const float* bhhb = (const float*)d_in[9];
    const float* bw1  = (const float*)d_in[10];
    const float* sw1  = (const float*)d_in[11];
    const float* sc1  = (const float*)d_in[12];
    const float* bw2  = (const float*)d_in[13];
    const float* sw2  = (const float*)d_in[14];
    const float* sc2  = (const float*)d_in[15];
    float* out = (float*)d_out;     // [0:512) = y, [512:) = a_1 (L,HID)

    float *gi_base, *A1, *W1, *A2, *W2, *a2;
    cudaGetSymbolAddress((void**)&gi_base, g_gi);
    cudaGetSymbolAddress((void**)&A1, g_A1);
    cudaGetSymbolAddress((void**)&W1, g_W1);
    cudaGetSymbolAddress((void**)&A2, g_A2);
    cudaGetSymbolAddress((void**)&W2, g_W2);
    cudaGetSymbolAddress((void**)&a2, g_a2);
    float* gi_f = gi_base;
    float* gi_b = gi_base + (size_t)LSEQ * TH3;

    k_init<<<8, 256>>>();

    // input-gate GEMMs: gi = h @ w_ih^T + b_ih
    dim3 ggi(TH3 / 128, LSEQ / 128);
    k_gemm<0><<<ggi, 256>>>(h, wihf, bihf, gi_f, LSEQ, TH3, HID);
    k_gemm<0><<<ggi, 256>>>(h, wihb, bihb, gi_b, LSEQ, TH3, HID);

    // recurrence, both directions concurrently
    k_gru<<<dim3(GB, 2), 256>>>(whhf, whhb, bhhf, bhhb);

    // KAN layer 1
    k_expand1<<<(LSEQ * 1024) / 256, 256>>>(A1);
    k_buildW<<<(HID * 1024 + 255) / 256, 256>>>(bw1, sw1, sc1, W1, 1024);
    k_gemm<1><<<dim3(HID / 128, LSEQ / 128), 256>>>(A1, W1, nullptr, out + HID, LSEQ, HID, KF1);

    // KAN layer 2
    k_expand2<<<(LSEQ * HID) / 256, 256>>>(out + HID, A2);
    k_buildW<<<(HID * HID + 255) / 256, 256>>>(bw2, sw2, sc2, W2, HID);
    k_gemm<2><<<dim3(HID / 128, LSEQ / 128), 256>>>(A2, W2, nullptr, a2, LSEQ, HID, KF2);

    // y = a2^T p (deterministic two-stage reduction)
    k_ypart<<<32, 512>>>(p);
    k_yfinal<<<2, 256>>>(out);
}